// round 4
// baseline (speedup 1.0000x reference)
#include <cuda_runtime.h>
#include <cuda_bf16.h>
#include <math.h>
#include <stdint.h>

// Problem constants
#define B  32768
#define K  8192
#define D  1024
#define DECAY   0.99f
#define ONE_M_D 0.01f
#define EPS     1e-5f
#define COMMIT  0.25f
#define NORM_EPS 1e-12f

// Output layout (flattened tuple, float32):
// z_q[B*D], code_ids[B], loss[1], new_codebook[K*D], new_count[K], new_weight[K*D]
#define OFF_ZQ   0
#define OFF_IDS  (B*D)                       // 33554432
#define OFF_LOSS (OFF_IDS + B)               // 33587200
#define OFF_CB   (OFF_LOSS + 1)              // 33587201  (ODD -> no float4 here)
#define OFF_CNT  (OFF_CB + K*D)              // 41975809
#define OFF_W    (OFF_CNT + K)               // 41984001  (ODD -> no float4 here)

// Scratch (device globals — no allocation allowed)
__device__ __align__(16) float g_cbn[K * D];      // normalized codebook
__device__ __align__(16) float g_wsum[K * D];     // segment sums of z
__device__ float g_cnt[K];          // segment counts (float)
__device__ float g_ncnt[K];         // new_count
__device__ int   g_ids[B];          // argmax ids
__device__ float g_loss;            // SSE accumulator

// ---------------------------------------------------------------------------
// Zero scratch accumulators
// ---------------------------------------------------------------------------
__global__ void k_zero() {
    int64_t tid = (int64_t)blockIdx.x * blockDim.x + threadIdx.x;
    int64_t stride = (int64_t)gridDim.x * blockDim.x;
    for (int64_t i = tid; i < (int64_t)K * D; i += stride) g_wsum[i] = 0.0f;
    for (int64_t i = tid; i < K; i += stride) g_cnt[i] = 0.0f;
    if (tid == 0) g_loss = 0.0f;
}

// ---------------------------------------------------------------------------
// Normalize codebook rows: cbn = cb / max(||cb||, 1e-12)  (one block per row)
// ---------------------------------------------------------------------------
__global__ void k_norm_cb(const float* __restrict__ cb) {
    __shared__ float red[256];
    int k = blockIdx.x;
    int t = threadIdx.x;
    const float4* row = (const float4*)(cb + (size_t)k * D);
    float4 v = row[t];                       // 256 threads x float4 = 1024
    float ss = v.x * v.x + v.y * v.y + v.z * v.z + v.w * v.w;
    red[t] = ss;
    __syncthreads();
    for (int s = 128; s > 0; s >>= 1) {
        if (t < s) red[t] += red[t + s];
        __syncthreads();
    }
    float denom = fmaxf(sqrtf(red[0]), NORM_EPS);
    float4 o;
    o.x = v.x / denom; o.y = v.y / denom; o.z = v.z / denom; o.w = v.w / denom;
    ((float4*)(g_cbn + (size_t)k * D))[t] = o;
}

// ---------------------------------------------------------------------------
// Fused sim GEMM + argmax.
// Each block: 128 z-rows, sweeps all K codewords (64 tiles of 128).
// 256 threads, 8x8 micro-tile, strided mapping: row = ty+16i, col = tx+16j.
// smem stride 129 -> conflict-free transposed stores and fragment loads.
// Note: z rows are NOT normalized — positive row scaling preserves argmax.
// ---------------------------------------------------------------------------
#define SM_STRIDE 129
__global__ __launch_bounds__(256, 2)
void k_argmax(const float* __restrict__ z) {
    __shared__ float sm[2 * 32 * SM_STRIDE];
    float* As = sm;
    float* Bs = sm + 32 * SM_STRIDE;

    int tid = threadIdx.x;
    int tx = tid & 15;
    int ty = tid >> 4;
    int row0 = blockIdx.x * 128;

    float best[8];
    int   bidx[8];
#pragma unroll
    for (int i = 0; i < 8; i++) { best[i] = -INFINITY; bidx[i] = 0x7fffffff; }

    for (int nt = 0; nt < K / 128; nt++) {
        float acc[8][8];
#pragma unroll
        for (int i = 0; i < 8; i++)
#pragma unroll
            for (int j = 0; j < 8; j++) acc[i][j] = 0.0f;

        const float* bbase = g_cbn + (size_t)nt * 128 * D;

        for (int d0 = 0; d0 < D; d0 += 32) {
#pragma unroll
            for (int p = 0; p < 4; p++) {
                int id = tid + 256 * p;          // 0..1023
                int m  = id >> 3;                // 0..127
                int kf = (id & 7) * 4;           // 0..28
                float4 av = *(const float4*)(z + (size_t)(row0 + m) * D + d0 + kf);
                As[(kf + 0) * SM_STRIDE + m] = av.x;
                As[(kf + 1) * SM_STRIDE + m] = av.y;
                As[(kf + 2) * SM_STRIDE + m] = av.z;
                As[(kf + 3) * SM_STRIDE + m] = av.w;
                float4 bv = *(const float4*)(bbase + (size_t)m * D + d0 + kf);
                Bs[(kf + 0) * SM_STRIDE + m] = bv.x;
                Bs[(kf + 1) * SM_STRIDE + m] = bv.y;
                Bs[(kf + 2) * SM_STRIDE + m] = bv.z;
                Bs[(kf + 3) * SM_STRIDE + m] = bv.w;
            }
            __syncthreads();
#pragma unroll
            for (int kk = 0; kk < 32; kk++) {
                float a[8], b[8];
#pragma unroll
                for (int i = 0; i < 8; i++) a[i] = As[kk * SM_STRIDE + ty + 16 * i];
#pragma unroll
                for (int j = 0; j < 8; j++) b[j] = Bs[kk * SM_STRIDE + tx + 16 * j];
#pragma unroll
                for (int i = 0; i < 8; i++)
#pragma unroll
                    for (int j = 0; j < 8; j++) acc[i][j] += a[i] * b[j];
            }
            __syncthreads();
        }

        // update running argmax (lowest index wins ties)
#pragma unroll
        for (int i = 0; i < 8; i++) {
#pragma unroll
            for (int j = 0; j < 8; j++) {
                int c = nt * 128 + tx + 16 * j;
                float v = acc[i][j];
                if (v > best[i] || (v == best[i] && c < bidx[i])) {
                    best[i] = v; bidx[i] = c;
                }
            }
        }
    }

    // Reduce across the 16 tx-threads that share each row.
    __syncthreads();
    float* sval = sm;                         // 128*16 floats
    int*   sidx = (int*)(sm + 2048);          // 128*16 ints
#pragma unroll
    for (int i = 0; i < 8; i++) {
        int r = ty + 16 * i;
        sval[r * 16 + tx] = best[i];
        sidx[r * 16 + tx] = bidx[i];
    }
    __syncthreads();
    if (tid < 128) {
        float bv = sval[tid * 16];
        int   bi = sidx[tid * 16];
        for (int t = 1; t < 16; t++) {
            float v = sval[tid * 16 + t];
            int   ix = sidx[tid * 16 + t];
            if (v > bv || (v == bv && ix < bi)) { bv = v; bi = ix; }
        }
        g_ids[row0 + tid] = bi;
    }
}

// ---------------------------------------------------------------------------
// Per-row: z_q = z + (q - z), SSE accumulation, segment count/sum scatter,
// ids written as float. One block (256 threads) per z row.
// ---------------------------------------------------------------------------
__global__ void k_scatter(const float* __restrict__ z,
                          const float* __restrict__ cb,
                          float* __restrict__ out) {
    __shared__ float red[256];
    int b = blockIdx.x;
    int t = threadIdx.x;
    int id = g_ids[b];

    const float4* zr = (const float4*)(z  + (size_t)b  * D);
    const float4* qr = (const float4*)(cb + (size_t)id * D);
    float4 zv = zr[t];
    float4 qv = qr[t];

    float4 zq;
    zq.x = zv.x + (qv.x - zv.x);
    zq.y = zv.y + (qv.y - zv.y);
    zq.z = zv.z + (qv.z - zv.z);
    zq.w = zv.w + (qv.w - zv.w);
    ((float4*)(out + OFF_ZQ + (size_t)b * D))[t] = zq;

    float dx = zv.x - qv.x, dy = zv.y - qv.y, dz = zv.z - qv.z, dw = zv.w - qv.w;
    red[t] = dx * dx + dy * dy + dz * dz + dw * dw;

    float* wrow = g_wsum + (size_t)id * D + t * 4;
    atomicAdd(wrow + 0, zv.x);
    atomicAdd(wrow + 1, zv.y);
    atomicAdd(wrow + 2, zv.z);
    atomicAdd(wrow + 3, zv.w);

    __syncthreads();
    for (int s = 128; s > 0; s >>= 1) {
        if (t < s) red[t] += red[t + s];
        __syncthreads();
    }
    if (t == 0) {
        atomicAdd(&g_loss, red[0]);
        atomicAdd(&g_cnt[id], 1.0f);
        out[OFF_IDS + b] = (float)id;
    }
}

// ---------------------------------------------------------------------------
// new_count = DECAY*ema_count + (1-DECAY)*n_k
// ---------------------------------------------------------------------------
__global__ void k_count(const float* __restrict__ ema_count,
                        float* __restrict__ out) {
    int k = blockIdx.x * blockDim.x + threadIdx.x;
    if (k < K) {
        float nc = DECAY * ema_count[k] + ONE_M_D * g_cnt[k];
        g_ncnt[k] = nc;
        out[OFF_CNT + k] = nc;
    }
}

// ---------------------------------------------------------------------------
// new_weight = DECAY*ema_weight + (1-DECAY)*sum_k ; new_codebook = w/(nc+eps)
// Vector loads from aligned sources; SCALAR stores to out (OFF_CB/OFF_W are
// odd element offsets -> float4 stores there trap with misaligned address).
// ---------------------------------------------------------------------------
__global__ void k_final(const float* __restrict__ ema_weight,
                        float* __restrict__ out) {
    int64_t i4 = (int64_t)blockIdx.x * blockDim.x + threadIdx.x;   // float4 index
    if (i4 >= (int64_t)K * D / 4) return;
    int row = (int)(i4 >> 8);                  // (i4*4)/1024
    float4 ew = ((const float4*)ema_weight)[i4];
    float4 ws = ((const float4*)g_wsum)[i4];
    float w0 = DECAY * ew.x + ONE_M_D * ws.x;
    float w1 = DECAY * ew.y + ONE_M_D * ws.y;
    float w2 = DECAY * ew.z + ONE_M_D * ws.z;
    float w3 = DECAY * ew.w + ONE_M_D * ws.w;
    int64_t base = i4 * 4;
    out[OFF_W + base + 0] = w0;
    out[OFF_W + base + 1] = w1;
    out[OFF_W + base + 2] = w2;
    out[OFF_W + base + 3] = w3;
    float denom = g_ncnt[row] + EPS;
    out[OFF_CB + base + 0] = w0 / denom;
    out[OFF_CB + base + 1] = w1 / denom;
    out[OFF_CB + base + 2] = w2 / denom;
    out[OFF_CB + base + 3] = w3 / denom;
}

__global__ void k_loss(float* __restrict__ out) {
    out[OFF_LOSS] = COMMIT * (g_loss / (float)((int64_t)B * D));
}

// ---------------------------------------------------------------------------
extern "C" void kernel_launch(void* const* d_in, const int* in_sizes, int n_in,
                              void* d_out, int out_size) {
    const float* z          = (const float*)d_in[0];
    const float* codebook   = (const float*)d_in[1];
    const float* ema_count  = (const float*)d_in[2];
    const float* ema_weight = (const float*)d_in[3];
    float* out = (float*)d_out;

    k_zero<<<2048, 256>>>();
    k_norm_cb<<<K, 256>>>(codebook);
    k_argmax<<<B / 128, 256>>>(z);
    k_scatter<<<B, 256>>>(z, codebook, out);
    k_count<<<(K + 255) / 256, 256>>>(ema_count, out);
    k_final<<<(K * D / 4 + 255) / 256, 256>>>(ema_weight, out);
    k_loss<<<1, 1>>>(out);
}

// round 7
// speedup vs baseline: 1.1377x; 1.1377x over previous
#include <cuda_runtime.h>
#include <cuda_bf16.h>
#include <math.h>
#include <stdint.h>

// Problem constants
#define B  32768
#define K  8192
#define D  1024
#define DECAY   0.99f
#define ONE_M_D 0.01f
#define EPS     1e-5f
#define COMMIT  0.25f
#define NORM_EPS 1e-12f

// Output layout (flattened tuple, float32)
#define OFF_ZQ   0
#define OFF_IDS  (B*D)
#define OFF_LOSS (OFF_IDS + B)
#define OFF_CB   (OFF_LOSS + 1)              // odd -> no float4 stores
#define OFF_CNT  (OFF_CB + K*D)
#define OFF_W    (OFF_CNT + K)               // odd -> no float4 stores

// -------------------- device scratch (no allocation allowed) ----------------
__device__ __align__(16) __nv_bfloat16 g_a0[(size_t)B * D];
__device__ __align__(16) __nv_bfloat16 g_a1[(size_t)B * D];
__device__ __align__(16) __nv_bfloat16 g_a2[(size_t)B * D];
__device__ __align__(16) __nv_bfloat16 g_b0[(size_t)K * D];
__device__ __align__(16) __nv_bfloat16 g_b1[(size_t)K * D];
__device__ __align__(16) __nv_bfloat16 g_b2[(size_t)K * D];
__device__ __align__(16) float g_wsum[K * D];
__device__ float g_cnt[K];
__device__ float g_ncnt[K];
__device__ int   g_ids[B];
__device__ float g_loss;

// -------------------- PTX helpers (arch-neutral, compute_103-safe) ----------
__device__ __forceinline__ uint32_t smem_u32(const void* p) {
    uint32_t a;
    asm("{ .reg .u64 t; cvta.to.shared.u64 t, %1; cvt.u32.u64 %0, t; }"
        : "=r"(a) : "l"(p));
    return a;
}
__device__ __forceinline__ void cp_async16(uint32_t dst, const void* src) {
    asm volatile("cp.async.cg.shared.global [%0], [%1], 16;"
                 :: "r"(dst), "l"(src) : "memory");
}
__device__ __forceinline__ void cp_commit() {
    asm volatile("cp.async.commit_group;" ::: "memory");
}
template <int N> __device__ __forceinline__ void cp_wait() {
    asm volatile("cp.async.wait_group %0;" :: "n"(N) : "memory");
}
// ldmatrix x4, non-transposed, b16
__device__ __forceinline__ void ldsm4(uint32_t& r0, uint32_t& r1,
                                      uint32_t& r2, uint32_t& r3, uint32_t a) {
    asm volatile("ldmatrix.sync.aligned.m8n8.x4.shared.b16 {%0,%1,%2,%3}, [%4];"
                 : "=r"(r0), "=r"(r1), "=r"(r2), "=r"(r3) : "r"(a));
}
// mma m16n8k16 bf16 -> f32 accumulate in place
__device__ __forceinline__ void mma16816(float* c, const uint32_t* a,
                                         const uint32_t* b) {
    asm volatile(
        "mma.sync.aligned.m16n8k16.row.col.f32.bf16.bf16.f32 "
        "{%0,%1,%2,%3}, {%4,%5,%6,%7}, {%8,%9}, {%0,%1,%2,%3};"
        : "+f"(c[0]), "+f"(c[1]), "+f"(c[2]), "+f"(c[3])
        : "r"(a[0]), "r"(a[1]), "r"(a[2]), "r"(a[3]), "r"(b[0]), "r"(b[1]));
}
#define SW128(x) ((x) ^ (((x) >> 3) & 0x70))

__device__ __forceinline__ void split3(float x, __nv_bfloat16& h0,
                                       __nv_bfloat16& h1, __nv_bfloat16& h2) {
    h0 = __float2bfloat16_rn(x);
    float r = x - __bfloat162float(h0);
    h1 = __float2bfloat16_rn(r);
    float r2 = r - __bfloat162float(h1);
    h2 = __float2bfloat16_rn(r2);
}

// -------------------- setup kernels -----------------------------------------
__global__ void k_zero() {
    int64_t tid = (int64_t)blockIdx.x * blockDim.x + threadIdx.x;
    int64_t stride = (int64_t)gridDim.x * blockDim.x;
    for (int64_t i = tid; i < (int64_t)K * D; i += stride) g_wsum[i] = 0.0f;
    for (int64_t i = tid; i < K; i += stride) g_cnt[i] = 0.0f;
    if (tid == 0) g_loss = 0.0f;
}

__global__ void k_split_z(const float* __restrict__ z) {
    int64_t i = (int64_t)blockIdx.x * blockDim.x + threadIdx.x;
    int64_t n4 = (int64_t)B * D / 4;
    int64_t stride = (int64_t)gridDim.x * blockDim.x;
    for (; i < n4; i += stride) {
        float4 v = ((const float4*)z)[i];
        __nv_bfloat16 a[4], b[4], c[4];
        split3(v.x, a[0], b[0], c[0]);
        split3(v.y, a[1], b[1], c[1]);
        split3(v.z, a[2], b[2], c[2]);
        split3(v.w, a[3], b[3], c[3]);
        __nv_bfloat162* p0 = (__nv_bfloat162*)g_a0 + i * 2;
        __nv_bfloat162* p1 = (__nv_bfloat162*)g_a1 + i * 2;
        __nv_bfloat162* p2 = (__nv_bfloat162*)g_a2 + i * 2;
        __nv_bfloat162 t;
        t.x = a[0]; t.y = a[1]; p0[0] = t; t.x = a[2]; t.y = a[3]; p0[1] = t;
        t.x = b[0]; t.y = b[1]; p1[0] = t; t.x = b[2]; t.y = b[3]; p1[1] = t;
        t.x = c[0]; t.y = c[1]; p2[0] = t; t.x = c[2]; t.y = c[3]; p2[1] = t;
    }
}

__global__ void k_split_cb(const float* __restrict__ cb) {
    __shared__ float red[256];
    int k = blockIdx.x;
    int t = threadIdx.x;
    float4 v = ((const float4*)(cb + (size_t)k * D))[t];
    red[t] = v.x * v.x + v.y * v.y + v.z * v.z + v.w * v.w;
    __syncthreads();
    for (int s = 128; s > 0; s >>= 1) {
        if (t < s) red[t] += red[t + s];
        __syncthreads();
    }
    float denom = fmaxf(sqrtf(red[0]), NORM_EPS);
    float e0 = v.x / denom, e1 = v.y / denom, e2 = v.z / denom, e3 = v.w / denom;
    __nv_bfloat16 a[4], b[4], c[4];
    split3(e0, a[0], b[0], c[0]);
    split3(e1, a[1], b[1], c[1]);
    split3(e2, a[2], b[2], c[2]);
    split3(e3, a[3], b[3], c[3]);
    size_t base2 = (size_t)k * (D / 2) + t * 2;
    __nv_bfloat162 x;
    x.x = a[0]; x.y = a[1]; ((__nv_bfloat162*)g_b0)[base2 + 0] = x;
    x.x = a[2]; x.y = a[3]; ((__nv_bfloat162*)g_b0)[base2 + 1] = x;
    x.x = b[0]; x.y = b[1]; ((__nv_bfloat162*)g_b1)[base2 + 0] = x;
    x.x = b[2]; x.y = b[3]; ((__nv_bfloat162*)g_b1)[base2 + 1] = x;
    x.x = c[0]; x.y = c[1]; ((__nv_bfloat162*)g_b2)[base2 + 0] = x;
    x.x = c[2]; x.y = c[3]; ((__nv_bfloat162*)g_b2)[base2 + 1] = x;
}

// -------------------- mma.sync GEMM + fused argmax --------------------------
// CTA: 128 z rows, sweep 64 N-tiles of 128 codewords. 8 warps = 4(M) x 2(N),
// warp tile 32x64. 6 split products accumulate into one fp32 acc[2][8][4].
// DKC=64, SW128 rows of 128B, 2-stage cp.async pipeline.
#define DKC   64
#define NDK   (D / DKC)               // 16
#define NT    (K / 128)               // 64
#define TILE_B 16384                  // 128 rows x 128 bytes
#define STAGE_B (6 * TILE_B)          // 96 KB
#define DYN_SMEM (2 * STAGE_B)

__global__ __launch_bounds__(256, 1)
void k_mma(int dummy) {
    extern __shared__ char dyn[];
    uint32_t sbase = smem_u32(dyn);

    int tid = threadIdx.x;
    int lane = tid & 31;
    int wid = tid >> 5;
    int warp_m = wid >> 1;            // 0..3
    int warp_n = wid & 1;             // 0..1
    int g = lane >> 2;                // 0..7
    int tig = lane & 3;               // 0..3
    int row0 = blockIdx.x * 128;

    // ldmatrix per-lane address pattern (identical for A and B operands):
    // r = tile_row0 + (lane & 15); byte col = k0*2 + (lane>>4)*16
    int lm_r = lane & 15;
    int lm_c = (lane >> 4) << 4;

    const __nv_bfloat16* asrc[3] = {
        g_a0 + (size_t)row0 * D, g_a1 + (size_t)row0 * D, g_a2 + (size_t)row0 * D };

    float best[4];
    int   bidx[4];
#pragma unroll
    for (int i = 0; i < 4; i++) { best[i] = -INFINITY; bidx[i] = 0x7fffffff; }

    for (int nt = 0; nt < NT; nt++) {
        const __nv_bfloat16* bsrc[3] = {
            g_b0 + (size_t)nt * 128 * D, g_b1 + (size_t)nt * 128 * D,
            g_b2 + (size_t)nt * 128 * D };

        float acc[2][8][4];
#pragma unroll
        for (int i = 0; i < 2; i++)
#pragma unroll
            for (int j = 0; j < 8; j++)
#pragma unroll
                for (int q = 0; q < 4; q++) acc[i][j][q] = 0.0f;

        // prologue: stage 0 <- dk 0
        {
            uint32_t sb = sbase;
#pragma unroll
            for (int t6 = 0; t6 < 6; t6++) {
                const __nv_bfloat16* src = (t6 < 3) ? asrc[t6] : bsrc[t6 - 3];
#pragma unroll
                for (int it = 0; it < 4; it++) {
                    int c = tid + 256 * it;
                    int r = c >> 3, ch = c & 7;
                    cp_async16(sb + t6 * TILE_B + SW128(r * 128 + ch * 16),
                               src + (size_t)r * D + ch * 8);
                }
            }
            cp_commit();
        }

        for (int dk = 0; dk < NDK; dk++) {
            int s = dk & 1;
            if (dk + 1 < NDK) {
                uint32_t sb = sbase + (s ^ 1) * STAGE_B;
                int koff = (dk + 1) * DKC;
#pragma unroll
                for (int t6 = 0; t6 < 6; t6++) {
                    const __nv_bfloat16* src =
                        ((t6 < 3) ? asrc[t6] : bsrc[t6 - 3]) + koff;
#pragma unroll
                    for (int it = 0; it < 4; it++) {
                        int c = tid + 256 * it;
                        int r = c >> 3, ch = c & 7;
                        cp_async16(sb + t6 * TILE_B + SW128(r * 128 + ch * 16),
                                   src + (size_t)r * D + ch * 8);
                    }
                }
                cp_commit();
                cp_wait<1>();
            } else {
                cp_wait<0>();
            }
            __syncthreads();

            uint32_t stg = sbase + s * STAGE_B;
            // 4 k16 steps within the 64-wide chunk
#pragma unroll
            for (int step = 0; step < 4; step++) {
                int kc = step * 32 + lm_c;   // byte col for this lane
                // A fragments: 3 splits x 2 m16 frags
                uint32_t afr[3][2][4];
#pragma unroll
                for (int sa = 0; sa < 3; sa++) {
#pragma unroll
                    for (int mi = 0; mi < 2; mi++) {
                        int r = warp_m * 32 + mi * 16 + lm_r;
                        uint32_t addr = stg + sa * TILE_B + SW128(r * 128 + kc);
                        ldsm4(afr[sa][mi][0], afr[sa][mi][1],
                              afr[sa][mi][2], afr[sa][mi][3], addr);
                    }
                }
                // loop over B splits; products grouped by b-split:
                // sb=0: a0,a1,a2 ; sb=1: a0,a1 ; sb=2: a0
#pragma unroll
                for (int sb = 0; sb < 3; sb++) {
                    uint32_t bfr[4][4];   // 4 ldsm4 -> 8 n-frags
#pragma unroll
                    for (int nb = 0; nb < 4; nb++) {
                        int r = warp_n * 64 + nb * 16 + lm_r;
                        uint32_t addr = stg + (3 + sb) * TILE_B +
                                        SW128(r * 128 + kc);
                        ldsm4(bfr[nb][0], bfr[nb][1], bfr[nb][2], bfr[nb][3],
                              addr);
                    }
                    int na = 3 - sb;     // how many a-splits pair with this b
#pragma unroll
                    for (int sa = 0; sa < 3; sa++) {
                        if (sa >= na) break;
#pragma unroll
                        for (int mi = 0; mi < 2; mi++) {
#pragma unroll
                            for (int nb = 0; nb < 4; nb++) {
                                // ldsm4 regs: 0=(n lo,k lo) 1=(n hi,k lo)
                                //             2=(n lo,k hi) 3=(n hi,k hi)
                                uint32_t b0[2] = { bfr[nb][0], bfr[nb][2] };
                                uint32_t b1[2] = { bfr[nb][1], bfr[nb][3] };
                                mma16816(acc[mi][nb * 2 + 0], afr[sa][mi], b0);
                                mma16816(acc[mi][nb * 2 + 1], afr[sa][mi], b1);
                            }
                        }
                    }
                }
            }
            __syncthreads();   // all warps done with stage s before overwrite
        }

        // epilogue: running argmax. thread owns 4 rows:
        // slot = i*2 + kk, row = warp_m*32 + i*16 + kk*8 + g
#pragma unroll
        for (int i = 0; i < 2; i++) {
#pragma unroll
            for (int kk = 0; kk < 2; kk++) {
                int slot = i * 2 + kk;
                float bv = best[slot];
                int   bi = bidx[slot];
#pragma unroll
                for (int j = 0; j < 8; j++) {
#pragma unroll
                    for (int h = 0; h < 2; h++) {
                        float v = acc[i][j][kk * 2 + h];
                        int c = nt * 128 + warp_n * 64 + j * 8 + tig * 2 + h;
                        if (v > bv || (v == bv && c < bi)) { bv = v; bi = c; }
                    }
                }
                best[slot] = bv; bidx[slot] = bi;
            }
        }
    }

    // final cross-thread reduction: 8 reducers per row
    __syncthreads();
    float* sval = (float*)dyn;                 // 128*8 floats
    int*   sidx = (int*)(dyn + 128 * 8 * 4);   // 128*8 ints
#pragma unroll
    for (int slot = 0; slot < 4; slot++) {
        int lrow = warp_m * 32 + (slot >> 1) * 16 + (slot & 1) * 8 + g;
        int col8 = warp_n * 4 + tig;
        sval[lrow * 8 + col8] = best[slot];
        sidx[lrow * 8 + col8] = bidx[slot];
    }
    __syncthreads();
    if (tid < 128) {
        float bv = sval[tid * 8];
        int   bi = sidx[tid * 8];
#pragma unroll
        for (int t = 1; t < 8; t++) {
            float v = sval[tid * 8 + t];
            int   ix = sidx[tid * 8 + t];
            if (v > bv || (v == bv && ix < bi)) { bv = v; bi = ix; }
        }
        g_ids[row0 + tid] = bi;
    }
}

// -------------------- epilogue kernels --------------------------------------
__global__ void k_scatter(const float* __restrict__ z,
                          const float* __restrict__ cb,
                          float* __restrict__ out) {
    __shared__ float red[256];
    int b = blockIdx.x;
    int t = threadIdx.x;
    int id = g_ids[b];

    float4 zv = ((const float4*)(z  + (size_t)b  * D))[t];
    float4 qv = ((const float4*)(cb + (size_t)id * D))[t];

    float4 zq;
    zq.x = zv.x + (qv.x - zv.x);
    zq.y = zv.y + (qv.y - zv.y);
    zq.z = zv.z + (qv.z - zv.z);
    zq.w = zv.w + (qv.w - zv.w);
    ((float4*)(out + OFF_ZQ + (size_t)b * D))[t] = zq;

    float dx = zv.x - qv.x, dy = zv.y - qv.y, dz = zv.z - qv.z, dw = zv.w - qv.w;
    red[t] = dx * dx + dy * dy + dz * dz + dw * dw;

    float* wrow = g_wsum + (size_t)id * D + t * 4;
    atomicAdd(wrow + 0, zv.x);
    atomicAdd(wrow + 1, zv.y);
    atomicAdd(wrow + 2, zv.z);
    atomicAdd(wrow + 3, zv.w);

    __syncthreads();
    for (int s = 128; s > 0; s >>= 1) {
        if (t < s) red[t] += red[t + s];
        __syncthreads();
    }
    if (t == 0) {
        atomicAdd(&g_loss, red[0]);
        atomicAdd(&g_cnt[id], 1.0f);
        out[OFF_IDS + b] = (float)id;
    }
}

__global__ void k_count(const float* __restrict__ ema_count,
                        float* __restrict__ out) {
    int k = blockIdx.x * blockDim.x + threadIdx.x;
    if (k < K) {
        float nc = DECAY * ema_count[k] + ONE_M_D * g_cnt[k];
        g_ncnt[k] = nc;
        out[OFF_CNT + k] = nc;
    }
}

__global__ void k_final(const float* __restrict__ ema_weight,
                        float* __restrict__ out) {
    int64_t i4 = (int64_t)blockIdx.x * blockDim.x + threadIdx.x;
    if (i4 >= (int64_t)K * D / 4) return;
    int row = (int)(i4 >> 8);
    float4 ew = ((const float4*)ema_weight)[i4];
    float4 ws = ((const float4*)g_wsum)[i4];
    float w0 = DECAY * ew.x + ONE_M_D * ws.x;
    float w1 = DECAY * ew.y + ONE_M_D * ws.y;
    float w2 = DECAY * ew.z + ONE_M_D * ws.z;
    float w3 = DECAY * ew.w + ONE_M_D * ws.w;
    int64_t base = i4 * 4;
    out[OFF_W + base + 0] = w0;
    out[OFF_W + base + 1] = w1;
    out[OFF_W + base + 2] = w2;
    out[OFF_W + base + 3] = w3;
    float denom = g_ncnt[row] + EPS;
    out[OFF_CB + base + 0] = w0 / denom;
    out[OFF_CB + base + 1] = w1 / denom;
    out[OFF_CB + base + 2] = w2 / denom;
    out[OFF_CB + base + 3] = w3 / denom;
}

__global__ void k_loss(float* __restrict__ out) {
    out[OFF_LOSS] = COMMIT * (g_loss / (float)((int64_t)B * D));
}

// ---------------------------------------------------------------------------
extern "C" void kernel_launch(void* const* d_in, const int* in_sizes, int n_in,
                              void* d_out, int out_size) {
    const float* z          = (const float*)d_in[0];
    const float* codebook   = (const float*)d_in[1];
    const float* ema_count  = (const float*)d_in[2];
    const float* ema_weight = (const float*)d_in[3];
    float* out = (float*)d_out;

    cudaFuncSetAttribute(k_mma, cudaFuncAttributeMaxDynamicSharedMemorySize,
                         DYN_SMEM);

    k_zero<<<2048, 256>>>();
    k_split_z<<<4096, 256>>>(z);
    k_split_cb<<<K, 256>>>(codebook);
    k_mma<<<B / 128, 256, DYN_SMEM>>>(0);
    k_scatter<<<B, 256>>>(z, codebook, out);
    k_count<<<(K + 255) / 256, 256>>>(ema_count, out);
    k_final<<<(K * D / 4 + 255) / 256, 256>>>(ema_weight, out);
    k_loss<<<1, 1>>>(out);
}

// round 8
// speedup vs baseline: 8.0653x; 7.0889x over previous
#include <cuda_runtime.h>
#include <cuda_bf16.h>
#include <math.h>
#include <stdint.h>

// Problem constants
#define B  32768
#define K  8192
#define D  1024
#define DECAY   0.99f
#define ONE_M_D 0.01f
#define EPS     1e-5f
#define COMMIT  0.25f
#define NORM_EPS 1e-12f

// Candidate machinery
#define CAP    64
#define MARGIN 0.15f

// Output layout (flattened tuple, float32)
#define OFF_ZQ   0
#define OFF_IDS  (B*D)
#define OFF_LOSS (OFF_IDS + B)
#define OFF_CB   (OFF_LOSS + 1)              // odd -> no float4 stores
#define OFF_CNT  (OFF_CB + K*D)
#define OFF_W    (OFF_CNT + K)               // odd -> no float4 stores

// -------------------- device scratch (no allocation allowed) ----------------
__device__ __align__(16) __nv_bfloat16 g_a0[(size_t)B * D];   // bf16(z)
__device__ __align__(16) __nv_bfloat16 g_b0[(size_t)K * D];   // bf16(cb_norm)
__device__ __align__(16) float g_cbn[(size_t)K * D];          // fp32 cb_norm
__device__ __align__(16) float g_wsum[K * D];
__device__ int   g_cand[(size_t)B * CAP];
__device__ int   g_ccnt[B];
__device__ float g_cnt[K];
__device__ float g_ncnt[K];
__device__ int   g_ids[B];
__device__ float g_loss;

// -------------------- PTX helpers (compute_103-safe) ------------------------
__device__ __forceinline__ uint32_t smem_u32(const void* p) {
    uint32_t a;
    asm("{ .reg .u64 t; cvta.to.shared.u64 t, %1; cvt.u32.u64 %0, t; }"
        : "=r"(a) : "l"(p));
    return a;
}
__device__ __forceinline__ void cp_async16(uint32_t dst, const void* src) {
    asm volatile("cp.async.cg.shared.global [%0], [%1], 16;"
                 :: "r"(dst), "l"(src) : "memory");
}
__device__ __forceinline__ void cp_commit() {
    asm volatile("cp.async.commit_group;" ::: "memory");
}
template <int N> __device__ __forceinline__ void cp_wait() {
    asm volatile("cp.async.wait_group %0;" :: "n"(N) : "memory");
}
__device__ __forceinline__ void ldsm4(uint32_t& r0, uint32_t& r1,
                                      uint32_t& r2, uint32_t& r3, uint32_t a) {
    asm volatile("ldmatrix.sync.aligned.m8n8.x4.shared.b16 {%0,%1,%2,%3}, [%4];"
                 : "=r"(r0), "=r"(r1), "=r"(r2), "=r"(r3) : "r"(a));
}
__device__ __forceinline__ void mma16816(float* c, const uint32_t* a,
                                         const uint32_t* b) {
    asm volatile(
        "mma.sync.aligned.m16n8k16.row.col.f32.bf16.bf16.f32 "
        "{%0,%1,%2,%3}, {%4,%5,%6,%7}, {%8,%9}, {%0,%1,%2,%3};"
        : "+f"(c[0]), "+f"(c[1]), "+f"(c[2]), "+f"(c[3])
        : "r"(a[0]), "r"(a[1]), "r"(a[2]), "r"(a[3]), "r"(b[0]), "r"(b[1]));
}
#define SW128(x) ((x) ^ (((x) >> 3) & 0x70))

// order-preserving float<->uint for atomicMax
__device__ __forceinline__ unsigned fenc(float f) {
    unsigned u = __float_as_uint(f);
    return (u & 0x80000000u) ? ~u : (u | 0x80000000u);
}
__device__ __forceinline__ float fdec(unsigned u) {
    return (u & 0x80000000u) ? __uint_as_float(u ^ 0x80000000u)
                             : __uint_as_float(~u);
}

// -------------------- setup kernels -----------------------------------------
__global__ void k_zero() {
    int64_t tid = (int64_t)blockIdx.x * blockDim.x + threadIdx.x;
    int64_t stride = (int64_t)gridDim.x * blockDim.x;
    for (int64_t i = tid; i < (int64_t)K * D; i += stride) g_wsum[i] = 0.0f;
    for (int64_t i = tid; i < K; i += stride) g_cnt[i] = 0.0f;
    for (int64_t i = tid; i < B; i += stride) g_ccnt[i] = 0;
    if (tid == 0) g_loss = 0.0f;
}

__global__ void k_cast_z(const float* __restrict__ z) {
    int64_t i = (int64_t)blockIdx.x * blockDim.x + threadIdx.x;
    int64_t n4 = (int64_t)B * D / 4;
    int64_t stride = (int64_t)gridDim.x * blockDim.x;
    for (; i < n4; i += stride) {
        float4 v = ((const float4*)z)[i];
        __nv_bfloat162* p = (__nv_bfloat162*)g_a0 + i * 2;
        __nv_bfloat162 t;
        t.x = __float2bfloat16_rn(v.x); t.y = __float2bfloat16_rn(v.y); p[0] = t;
        t.x = __float2bfloat16_rn(v.z); t.y = __float2bfloat16_rn(v.w); p[1] = t;
    }
}

// normalize codebook rows -> fp32 g_cbn + bf16 g_b0. one block per row.
__global__ void k_norm_cb(const float* __restrict__ cb) {
    __shared__ float red[256];
    int k = blockIdx.x;
    int t = threadIdx.x;
    float4 v = ((const float4*)(cb + (size_t)k * D))[t];
    red[t] = v.x * v.x + v.y * v.y + v.z * v.z + v.w * v.w;
    __syncthreads();
    for (int s = 128; s > 0; s >>= 1) {
        if (t < s) red[t] += red[t + s];
        __syncthreads();
    }
    float denom = fmaxf(sqrtf(red[0]), NORM_EPS);
    float4 o;
    o.x = v.x / denom; o.y = v.y / denom; o.z = v.z / denom; o.w = v.w / denom;
    ((float4*)(g_cbn + (size_t)k * D))[t] = o;
    __nv_bfloat162* p = (__nv_bfloat162*)g_b0 + (size_t)k * (D / 2) + t * 2;
    __nv_bfloat162 x;
    x.x = __float2bfloat16_rn(o.x); x.y = __float2bfloat16_rn(o.y); p[0] = x;
    x.x = __float2bfloat16_rn(o.z); x.y = __float2bfloat16_rn(o.w); p[1] = x;
}

// -------------------- approx bf16 GEMM + candidate harvest ------------------
// CTA: 128 rows, sweeps 64 N-tiles of 128. 8 warps = 4(M) x 2(N), warp 32x64.
// Single bf16 product. Running per-row max in smem; values within MARGIN of
// the running max are appended to the row's global candidate list.
#define DKC   64
#define NDK   (D / DKC)               // 16
#define NT    (K / 128)               // 64
#define TILE_B 16384                  // 128 rows x 128 bytes
#define STAGE_B (2 * TILE_B)          // A tile + B tile = 32 KB
#define DYN_SMEM (2 * STAGE_B)        // 64 KB

__global__ __launch_bounds__(256, 2)
void k_approx(int dummy) {
    extern __shared__ char dyn[];
    __shared__ unsigned srowmax[128];
    uint32_t sbase = smem_u32(dyn);

    int tid = threadIdx.x;
    int lane = tid & 31;
    int wid = tid >> 5;
    int warp_m = wid >> 1;            // 0..3
    int warp_n = wid & 1;             // 0..1
    int g = lane >> 2;                // 0..7
    int tig = lane & 3;               // 0..3
    int row0 = blockIdx.x * 128;

    int lm_r = lane & 15;
    int lm_c = (lane >> 4) << 4;

    if (tid < 128) srowmax[tid] = 0u;   // < fenc of any float
    __syncthreads();

    const __nv_bfloat16* asrc0 = g_a0 + (size_t)row0 * D;

    for (int nt = 0; nt < NT; nt++) {
        const __nv_bfloat16* bsrc0 = g_b0 + (size_t)nt * 128 * D;

        float acc[2][8][4];
#pragma unroll
        for (int i = 0; i < 2; i++)
#pragma unroll
            for (int j = 0; j < 8; j++)
#pragma unroll
                for (int q = 0; q < 4; q++) acc[i][j][q] = 0.0f;

        // prologue: stage 0 <- dk 0 (A tile + B tile)
        {
            uint32_t sb = sbase;
#pragma unroll
            for (int t2 = 0; t2 < 2; t2++) {
                const __nv_bfloat16* src = t2 ? bsrc0 : asrc0;
#pragma unroll
                for (int it = 0; it < 4; it++) {
                    int c = tid + 256 * it;
                    int r = c >> 3, ch = c & 7;
                    cp_async16(sb + t2 * TILE_B + SW128(r * 128 + ch * 16),
                               src + (size_t)r * D + ch * 8);
                }
            }
            cp_commit();
        }

        for (int dk = 0; dk < NDK; dk++) {
            int s = dk & 1;
            if (dk + 1 < NDK) {
                uint32_t sb = sbase + (s ^ 1) * STAGE_B;
                int koff = (dk + 1) * DKC;
#pragma unroll
                for (int t2 = 0; t2 < 2; t2++) {
                    const __nv_bfloat16* src = (t2 ? bsrc0 : asrc0) + koff;
#pragma unroll
                    for (int it = 0; it < 4; it++) {
                        int c = tid + 256 * it;
                        int r = c >> 3, ch = c & 7;
                        cp_async16(sb + t2 * TILE_B + SW128(r * 128 + ch * 16),
                                   src + (size_t)r * D + ch * 8);
                    }
                }
                cp_commit();
                cp_wait<1>();
            } else {
                cp_wait<0>();
            }
            __syncthreads();

            uint32_t stg = sbase + s * STAGE_B;
#pragma unroll
            for (int step = 0; step < 4; step++) {
                int kc = step * 32 + lm_c;
                uint32_t afr[2][4];
#pragma unroll
                for (int mi = 0; mi < 2; mi++) {
                    int r = warp_m * 32 + mi * 16 + lm_r;
                    uint32_t addr = stg + SW128(r * 128 + kc);
                    ldsm4(afr[mi][0], afr[mi][1], afr[mi][2], afr[mi][3], addr);
                }
                uint32_t bfr[4][4];
#pragma unroll
                for (int nb = 0; nb < 4; nb++) {
                    int r = warp_n * 64 + nb * 16 + lm_r;
                    uint32_t addr = stg + TILE_B + SW128(r * 128 + kc);
                    ldsm4(bfr[nb][0], bfr[nb][1], bfr[nb][2], bfr[nb][3], addr);
                }
#pragma unroll
                for (int mi = 0; mi < 2; mi++) {
#pragma unroll
                    for (int nb = 0; nb < 4; nb++) {
                        uint32_t b0[2] = { bfr[nb][0], bfr[nb][2] };
                        uint32_t b1[2] = { bfr[nb][1], bfr[nb][3] };
                        mma16816(acc[mi][nb * 2 + 0], afr[mi], b0);
                        mma16816(acc[mi][nb * 2 + 1], afr[mi], b1);
                    }
                }
            }
            __syncthreads();
        }

        // ---- epilogue: running max + candidate insert
#pragma unroll
        for (int i = 0; i < 2; i++) {
#pragma unroll
            for (int kk = 0; kk < 2; kk++) {
                int lrow = warp_m * 32 + i * 16 + kk * 8 + g;
                float m = -INFINITY;
#pragma unroll
                for (int j = 0; j < 8; j++) {
                    m = fmaxf(m, acc[i][j][kk * 2 + 0]);
                    m = fmaxf(m, acc[i][j][kk * 2 + 1]);
                }
                atomicMax(&srowmax[lrow], fenc(m));
            }
        }
        __syncthreads();
#pragma unroll
        for (int i = 0; i < 2; i++) {
#pragma unroll
            for (int kk = 0; kk < 2; kk++) {
                int lrow = warp_m * 32 + i * 16 + kk * 8 + g;
                float thr = fdec(srowmax[lrow]) - MARGIN;
#pragma unroll
                for (int j = 0; j < 8; j++) {
#pragma unroll
                    for (int h = 0; h < 2; h++) {
                        float v = acc[i][j][kk * 2 + h];
                        if (v >= thr) {
                            int col = nt * 128 + warp_n * 64 + j * 8 + tig * 2 + h;
                            int grow = row0 + lrow;
                            int p = atomicAdd(&g_ccnt[grow], 1);
                            if (p < CAP) g_cand[(size_t)grow * CAP + p] = col;
                        }
                    }
                }
            }
        }
        // no extra sync needed: next iteration's __syncthreads orders everything
    }
}

// -------------------- exact rescore: one warp per row -----------------------
__global__ __launch_bounds__(256)
void k_rescore(const float* __restrict__ z) {
    int row = blockIdx.x * 8 + (threadIdx.x >> 5);
    int lane = threadIdx.x & 31;
    int cnt = g_ccnt[row];
    if (cnt > CAP) cnt = CAP;

    float4 zr[8];
    const float4* zp = (const float4*)(z + (size_t)row * D);
#pragma unroll
    for (int i = 0; i < 8; i++) zr[i] = zp[i * 32 + lane];

    float bv = -INFINITY;
    int   bi = 0;
    for (int c = 0; c < cnt; c++) {
        int idx = g_cand[(size_t)row * CAP + c];
        const float4* cp = (const float4*)(g_cbn + (size_t)idx * D);
        float s = 0.0f;
#pragma unroll
        for (int i = 0; i < 8; i++) {
            float4 cv = cp[i * 32 + lane];
            s += zr[i].x * cv.x + zr[i].y * cv.y + zr[i].z * cv.z + zr[i].w * cv.w;
        }
#pragma unroll
        for (int o = 16; o > 0; o >>= 1) s += __shfl_xor_sync(0xFFFFFFFFu, s, o);
        if (s > bv || (s == bv && idx < bi)) { bv = s; bi = idx; }
    }
    if (lane == 0) g_ids[row] = bi;
}

// -------------------- epilogue kernels --------------------------------------
__global__ void k_scatter(const float* __restrict__ z,
                          const float* __restrict__ cb,
                          float* __restrict__ out) {
    __shared__ float red[256];
    int b = blockIdx.x;
    int t = threadIdx.x;
    int id = g_ids[b];

    float4 zv = ((const float4*)(z  + (size_t)b  * D))[t];
    float4 qv = ((const float4*)(cb + (size_t)id * D))[t];

    float4 zq;
    zq.x = zv.x + (qv.x - zv.x);
    zq.y = zv.y + (qv.y - zv.y);
    zq.z = zv.z + (qv.z - zv.z);
    zq.w = zv.w + (qv.w - zv.w);
    ((float4*)(out + OFF_ZQ + (size_t)b * D))[t] = zq;

    float dx = zv.x - qv.x, dy = zv.y - qv.y, dz = zv.z - qv.z, dw = zv.w - qv.w;
    red[t] = dx * dx + dy * dy + dz * dz + dw * dw;

    float* wrow = g_wsum + (size_t)id * D + t * 4;
    atomicAdd(wrow + 0, zv.x);
    atomicAdd(wrow + 1, zv.y);
    atomicAdd(wrow + 2, zv.z);
    atomicAdd(wrow + 3, zv.w);

    __syncthreads();
    for (int s = 128; s > 0; s >>= 1) {
        if (t < s) red[t] += red[t + s];
        __syncthreads();
    }
    if (t == 0) {
        atomicAdd(&g_loss, red[0]);
        atomicAdd(&g_cnt[id], 1.0f);
        out[OFF_IDS + b] = (float)id;
    }
}

__global__ void k_count(const float* __restrict__ ema_count,
                        float* __restrict__ out) {
    int k = blockIdx.x * blockDim.x + threadIdx.x;
    if (k < K) {
        float nc = DECAY * ema_count[k] + ONE_M_D * g_cnt[k];
        g_ncnt[k] = nc;
        out[OFF_CNT + k] = nc;
    }
}

__global__ void k_final(const float* __restrict__ ema_weight,
                        float* __restrict__ out) {
    int64_t i4 = (int64_t)blockIdx.x * blockDim.x + threadIdx.x;
    if (i4 >= (int64_t)K * D / 4) return;
    int row = (int)(i4 >> 8);
    float4 ew = ((const float4*)ema_weight)[i4];
    float4 ws = ((const float4*)g_wsum)[i4];
    float w0 = DECAY * ew.x + ONE_M_D * ws.x;
    float w1 = DECAY * ew.y + ONE_M_D * ws.y;
    float w2 = DECAY * ew.z + ONE_M_D * ws.z;
    float w3 = DECAY * ew.w + ONE_M_D * ws.w;
    int64_t base = i4 * 4;
    out[OFF_W + base + 0] = w0;
    out[OFF_W + base + 1] = w1;
    out[OFF_W + base + 2] = w2;
    out[OFF_W + base + 3] = w3;
    float denom = g_ncnt[row] + EPS;
    out[OFF_CB + base + 0] = w0 / denom;
    out[OFF_CB + base + 1] = w1 / denom;
    out[OFF_CB + base + 2] = w2 / denom;
    out[OFF_CB + base + 3] = w3 / denom;
}

__global__ void k_loss(float* __restrict__ out) {
    out[OFF_LOSS] = COMMIT * (g_loss / (float)((int64_t)B * D));
}

// ---------------------------------------------------------------------------
extern "C" void kernel_launch(void* const* d_in, const int* in_sizes, int n_in,
                              void* d_out, int out_size) {
    const float* z          = (const float*)d_in[0];
    const float* codebook   = (const float*)d_in[1];
    const float* ema_count  = (const float*)d_in[2];
    const float* ema_weight = (const float*)d_in[3];
    float* out = (float*)d_out;

    cudaFuncSetAttribute(k_approx, cudaFuncAttributeMaxDynamicSharedMemorySize,
                         DYN_SMEM);

    k_zero<<<2048, 256>>>();
    k_cast_z<<<4096, 256>>>(z);
    k_norm_cb<<<K, 256>>>(codebook);
    k_approx<<<B / 128, 256, DYN_SMEM>>>(0);
    k_rescore<<<B / 8, 256>>>(z);
    k_scatter<<<B, 256>>>(z, codebook, out);
    k_count<<<(K + 255) / 256, 256>>>(ema_count, out);
    k_final<<<(K * D / 4 + 255) / 256, 256>>>(ema_weight, out);
    k_loss<<<1, 1>>>(out);
}